// round 6
// baseline (speedup 1.0000x reference)
#include <cuda_runtime.h>
#include <math.h>

// SpikingLayer T=500, B*N=65536. Two-kernel scheme:
//  K1 (pack): x f32 -> bit-packed g_pk (float4/uint4 vectorized), DRAM-bound.
//  K2 (scan): per-neuron 500-step scan, BLK=128 so warps cover all 4 SMSPs
//     (wid%4 mapping starved SMSP 2/3 at BLK=64). No input loads in hot loop;
//     5 packed words per 32-step group, lag-50/100 taps via funnel-shifted
//     composite words (one LOP3 test per tap per step).
//  Decision logic identical to the R3-R5 passing kernels:
//    - 2nd-order IIR approximates the 149-tap EPSP conv (err << 1e-3)
//    - |u-1| < 1e-3 => recompute with the reference's exact f32 rounding
//      (sum k[j] over set history bits, lag j descending 148..0, f32 adds).

#define TBN 65536
#define T_STEPS 500
#define PADW 8          // leading zero words (history before t=0)
#define NW 16           // ceil(500/32)
#define MARGIN 1e-3f
#define BLK 128

__device__ unsigned g_pk[(PADW + NW) * TBN];   // 6 MB static scratch

// ---------------- K1: pack binary input into bits (+ zero pad) ----------------
__global__ __launch_bounds__(256)
void pack_kernel(const float4* __restrict__ x4) {
    const int tid = blockIdx.x * 256 + threadIdx.x;   // (PADW+NW)*TBN/4 threads
    const int n4 = tid & (TBN / 4 - 1);               // group of 4 neurons
    const int wq = tid >> 14;
    uint4 acc = make_uint4(0u, 0u, 0u, 0u);
    if (wq >= PADW) {
        const int q = wq - PADW;
        const float4* p = x4 + (size_t)(32 * q) * (TBN / 4) + n4;
        #pragma unroll
        for (int i = 0; i < 32; i++) {
            if (32 * q + i < T_STEPS) {
                float4 v = __ldcs(p + (size_t)i * (TBN / 4));
                acc.x |= (v.x != 0.0f) ? (1u << i) : 0u;
                acc.y |= (v.y != 0.0f) ? (1u << i) : 0u;
                acc.z |= (v.z != 0.0f) ? (1u << i) : 0u;
                acc.w |= (v.w != 0.0f) ? (1u << i) : 0u;
            }
        }
    }
    __stcs(reinterpret_cast<uint4*>(g_pk) + (size_t)wq * (TBN / 4) + n4, acc);
}

// ------------- exact near-threshold recompute (reference rounding) -------------
__device__ __noinline__ float exact_vmem(const unsigned* __restrict__ pk0, int t,
                                         const float* __restrict__ ks) {
    float acc = 0.0f;
    #pragma unroll
    for (int w = 4; w >= 0; w--) {           // oldest lag window first
        int e = t - 32 * w;                  // newest time in this window
        int q = e >> 5;
        int p = e & 31;
        unsigned lo = __ldg(pk0 + (ptrdiff_t)(q - 1) * TBN);
        unsigned hi = __ldg(pk0 + (ptrdiff_t)q * TBN);
        unsigned W  = __funnelshift_rc(lo, hi, p + 1);  // times e-31..e at bits 0..31
        unsigned m  = __brev(W);             // bit b = x[t - 32w - b]
        if (w == 4) m &= 0x001FFFFFu;        // lags <= 148
        while (m) {                          // descending lag order
            unsigned b = 31u - __clz(m);
            acc += ks[32 * w + b];
            m &= ~(1u << b);
        }
    }
    return acc;
}

// ---------------- K2: per-neuron scan, no input loads in hot loop --------------
template <int CNT>
__device__ __forceinline__ void run_group(
    int g, const unsigned* __restrict__ pk0, float* __restrict__ op,
    const float* __restrict__ ks, float& v1, float& v2, float& r)
{
    const float c1    = 1.7235681711139413f;     // a + b   (a=e^-0.2, b=e^-0.1)
    const float c2    = -0.7408182206817179f;    // -ab = -e^-0.3
    const float A     = 4.5399929762484854e-05f; // a^50 = b^100 = e^-10
    const float alpha = 0.9048374180359595f;     // e^-0.1

    const unsigned wg   = __ldg(pk0 + (ptrdiff_t)g * TBN);
    const unsigned wgm1 = __ldg(pk0 + (ptrdiff_t)(g - 1) * TBN);
    const unsigned wgm2 = __ldg(pk0 + (ptrdiff_t)(g - 2) * TBN);
    const unsigned wgm3 = __ldg(pk0 + (ptrdiff_t)(g - 3) * TBN);
    const unsigned wgm4 = __ldg(pk0 + (ptrdiff_t)(g - 4) * TBN);
    // composite lag words: bit i = x[tbase + i - 50] / x[tbase + i - 100]
    const unsigned W50  = __funnelshift_rc(wgm2, wgm1, 14);
    const unsigned W100 = __funnelshift_rc(wgm4, wgm3, 28);

    const int tbase = 32 * g;
    float* o = op + (size_t)tbase * TBN;

    #pragma unroll
    for (int i = 0; i < CNT; i++) {
        const float xf = (wg & (1u << i)) ? 1.0f : 0.0f;

        float v = fmaf(c1, v1, fmaf(c2, v2, xf));
        v -= (W50  & (1u << i)) ? A : 0.0f;   // x[t-50]
        v -= (W100 & (1u << i)) ? A : 0.0f;   // x[t-100]
        v2 = v1; v1 = v;

        float u = v + r;
        if (__builtin_expect(fabsf(u - 1.0f) < MARGIN, 0))
            u = exact_vmem(pk0, tbase + i, ks) + r;

        float s = (u >= 1.0f) ? 1.0f : 0.0f;
        r = (r - s) * alpha;
        __stcs(o + (size_t)i * TBN, s);
    }
}

__global__ __launch_bounds__(BLK)
void SpikingLayer_90202903151092_kernel(const float* __restrict__ ker,
                                        float* __restrict__ out) {
    __shared__ float ks[152];
    for (int i = threadIdx.x; i < 149; i += BLK) ks[i] = ker[i];
    __syncthreads();

    const int n = blockIdx.x * BLK + threadIdx.x;
    const unsigned* pk0 = g_pk + (size_t)PADW * TBN + n;   // word q=0
    float* op = out + n;

    float v1 = 0.0f, v2 = 0.0f, r = 0.0f;

    #pragma unroll 1
    for (int g = 0; g < 15; g++)
        run_group<32>(g, pk0, op, ks, v1, v2, r);
    run_group<20>(15, pk0, op, ks, v1, v2, r);   // t = 480..499
}

extern "C" void kernel_launch(void* const* d_in, const int* in_sizes, int n_in,
                              void* d_out, int out_size) {
    const float* x   = (const float*)d_in[0];  // binary_input (500,16,1,4096) f32
    const float* ker = (const float*)d_in[1];  // epsp_kernel (1,149) f32
    float* out = (float*)d_out;                // spikes (500,16,4096) f32
    pack_kernel<<<(PADW + NW) * (TBN / 4) / 256, 256>>>((const float4*)x);
    SpikingLayer_90202903151092_kernel<<<TBN / BLK, BLK>>>(ker, out);
}